// round 10
// baseline (speedup 1.0000x reference)
#include <cuda_runtime.h>
#include <math.h>

#define BATCH 256
#define TLEN  50
#define NOBS  8192
#define NKC   50

// ---- device-global scratch (no allocations allowed) ----
__device__ unsigned char g_assign[NOBS];                 // assign[] as uint8
__device__ float         g_probs_scratch[BATCH * TLEN];  // fallback sink

__device__ __forceinline__ float sigm(float x) {
    return 1.0f / (1.0f + __expf(-x));
}

// ============================================================
// k1: recover assign[] from one-hot A. Triggers programmatic
// launch completion IMMEDIATELY so k2's independent prologue
// overlaps this kernel's DRAM scan.
// ============================================================
__global__ __launch_bounds__(256)
void k1_prep(const float4* __restrict__ A4) {
    cudaTriggerProgrammaticLaunchCompletion();

    const int half = NOBS * NKC / 8;              // 51200 float4s per half
    int idx = blockIdx.x * 256 + threadIdx.x;
    float4 v0 = A4[idx];
    float4 v1 = A4[idx + half];

    int b0 = idx * 4;
    if (v0.x > 0.5f) { int i = b0 + 0; g_assign[i / NKC] = (unsigned char)(i % NKC); }
    if (v0.y > 0.5f) { int i = b0 + 1; g_assign[i / NKC] = (unsigned char)(i % NKC); }
    if (v0.z > 0.5f) { int i = b0 + 2; g_assign[i / NKC] = (unsigned char)(i % NKC); }
    if (v0.w > 0.5f) { int i = b0 + 3; g_assign[i / NKC] = (unsigned char)(i % NKC); }

    int b1 = (idx + half) * 4;
    if (v1.x > 0.5f) { int i = b1 + 0; g_assign[i / NKC] = (unsigned char)(i % NKC); }
    if (v1.y > 0.5f) { int i = b1 + 1; g_assign[i / NKC] = (unsigned char)(i % NKC); }
    if (v1.z > 0.5f) { int i = b1 + 2; g_assign[i / NKC] = (unsigned char)(i % NKC); }
    if (v1.w > 0.5f) { int i = b1 + 3; g_assign[i / NKC] = (unsigned char)(i % NKC); }
}

// ============================================================
// k2: fused BKT, one block (256 thr) per batch row.
//  Phase 0 (overlaps k1 via PDL): scalar row loads + all sigmoids.
//  cudaGridDependencySynchronize() -> g_assign valid.
//  Phase 1: g_assign -> shared copy (2 int4/thread).
//  Phase 2: LDS-only gathers build per-step Moebius tables.
//  Phase 3: parallel Moebius composition (passes A and B on
//           separate warps, unroll 7, branch-free).
//  Phase 4: expansion, 8 float4 stores/thread.
// ============================================================
__global__ __launch_bounds__(256)
void k2_fused(const int*   __restrict__ prev_kc,
              const int*   __restrict__ curr_kc,
              const float* __restrict__ prev_corr,
              const float* __restrict__ kc_logits,
              float*       __restrict__ probs_out,
              float*       __restrict__ state_out,
              int do_state) {
    __shared__ unsigned char s_assign[NOBS];   // 8 KB
    __shared__ float4        s_pr[NKC];        // sigmoid(pl,pf,p2,p3)
    __shared__ float         s_p4[NKC];        // initial state per KC
    __shared__ float4        s_M[TLEN];        // Moebius (A,B,C,D) per step
    __shared__ float2        s_ozw[TLEN];      // (q3-q2, q2) at ack KC
    __shared__ float         s_state[NKC];     // final compact state
    __shared__ unsigned char s_ap[TLEN];
    __shared__ unsigned char s_ack[TLEN];

    const int b   = blockIdx.x;
    const int tid = threadIdx.x;

    // ---- phase 0: everything independent of g_assign ----
    int   pkv = 0, ckv = 0;
    float cr  = 0.0f;
    if (tid < TLEN) {
        pkv = prev_kc[b * TLEN + tid];
        ckv = curr_kc[b * TLEN + tid];
        cr  = prev_corr[b * TLEN + tid];

        float4 p;
        p.x = sigm(kc_logits[tid * 5 + 0]);
        p.y = sigm(kc_logits[tid * 5 + 1]);
        p.z = sigm(kc_logits[tid * 5 + 2]);
        p.w = sigm(kc_logits[tid * 5 + 3]);
        s_pr[tid] = p;
        s_p4[tid] = sigm(kc_logits[tid * 5 + 4]);
    }

    // ---- wait for k1 (PDL edge) ----
    cudaGridDependencySynchronize();

    // ---- phase 1: g_assign -> shared (coalesced int4) ----
    {
        const int4* src = (const int4*)g_assign;
        int4*       dst = (int4*)s_assign;
        dst[tid]       = src[tid];
        dst[tid + 256] = src[tid + 256];
    }
    __syncthreads();

    // ---- phase 2: per-step tables, LDS-only gathers ----
    if (tid < TLEN) {
        int ap = s_assign[pkv];
        int ac = s_assign[ckv];
        s_ap[tid]  = (unsigned char)ap;
        s_ack[tid] = (unsigned char)ac;

        float4 pp = s_pr[ap];
        float o0, o1;
        if (cr > 0.5f) { o0 = pp.z;        o1 = pp.w;        }
        else           { o0 = 1.0f - pp.z; o1 = 1.0f - pp.w; }
        float d10 = o1 - o0;
        float c1  = 1.0f - pp.y - pp.x;
        // pred = (A*s + B) / (C*s + D)
        s_M[tid] = make_float4(fmaf(pp.x, d10, c1 * o1), pp.x * o0, d10, o0);

        float4 q = s_pr[ac];
        s_ozw[tid] = make_float2(q.w - q.z, q.z);
    }
    __syncthreads();

    // ---- phase 3: parallel Moebius composition ----
    if (tid < TLEN) {
        // pass A: out[t], t = tid (t=0 -> identity)
        const int t = tid;
        const int k = (int)s_ack[t];
        float a = 1.0f, bm = 0.0f, c = 0.0f, d = 1.0f;
        #pragma unroll 7
        for (int i = 1; i < TLEN; i++) {
            float4 M = s_M[i];                            // broadcast LDS
            bool take = (i <= t) && ((int)s_ap[i] == k);
            float Mx = take ? M.x : 1.0f;
            float My = take ? M.y : 0.0f;
            float Mz = take ? M.z : 0.0f;
            float Mw = take ? M.w : 1.0f;
            float na = fmaf(Mx, a,  My * c);
            float nb = fmaf(Mx, bm, My * d);
            float nc = fmaf(Mz, a,  Mw * c);
            float nd = fmaf(Mz, bm, Mw * d);
            a = na; bm = nb; c = nc; d = nd;
        }
        float s0 = s_p4[k];
        float sf = __fdividef(fmaf(a, s0, bm), fmaf(c, s0, d));
        float2 zw = s_ozw[t];
        probs_out[b * TLEN + t] = fmaf(zw.x, sf, zw.y);
    } else if (tid >= 64 && tid < 64 + NKC) {
        // pass B: final state[k], k = tid-64 (separate warps)
        const int k = tid - 64;
        float a = 1.0f, bm = 0.0f, c = 0.0f, d = 1.0f;
        #pragma unroll 7
        for (int i = 1; i < TLEN; i++) {
            float4 M = s_M[i];
            bool take = ((int)s_ap[i] == k);
            float Mx = take ? M.x : 1.0f;
            float My = take ? M.y : 0.0f;
            float Mz = take ? M.z : 0.0f;
            float Mw = take ? M.w : 1.0f;
            float na = fmaf(Mx, a,  My * c);
            float nb = fmaf(Mx, bm, My * d);
            float nc = fmaf(Mz, a,  Mw * c);
            float nd = fmaf(Mz, bm, Mw * d);
            a = na; bm = nb; c = nc; d = nd;
        }
        float s0 = s_p4[k];
        s_state[k] = __fdividef(fmaf(a, s0, bm), fmaf(c, s0, d));
    }
    __syncthreads();

    // ---- phase 4: expansion, 8 float4 stores/thread ----
    if (do_state) {
        float4*       o  = (float4*)(state_out + (size_t)b * NOBS);
        const uchar4* a4 = (const uchar4*)s_assign;
        #pragma unroll
        for (int j = 0; j < 8; j++) {
            uchar4 a = a4[tid + 256 * j];
            o[tid + 256 * j] =
                make_float4(s_state[a.x], s_state[a.y], s_state[a.z], s_state[a.w]);
        }
    }
}

// ============================================================
extern "C" void kernel_launch(void* const* d_in, const int* in_sizes, int n_in,
                              void* d_out, int out_size) {
    const int*    prev_kc   = (const int*)   d_in[0];
    const int*    curr_kc   = (const int*)   d_in[1];
    const float*  prev_corr = (const float*) d_in[2];
    const float*  kc_logits = (const float*) d_in[3];
    const float4* A4        = (const float4*)d_in[4];
    float*        out       = (float*)d_out;

    k1_prep<<<(NOBS * NKC / 8) / 256, 256>>>(A4);

    // Output layout: [probs (256*50) | state (256*8192)] concatenated.
    float* probs_out = out;
    float* state_out = out + BATCH * TLEN;
    int    do_state  = 1;

    if (out_size == BATCH * TLEN) {
        do_state  = 0;
        state_out = out;                 // unused
    } else if (out_size == BATCH * NOBS) {
        void* scratch = nullptr;
        cudaGetSymbolAddress(&scratch, g_probs_scratch);
        probs_out = (float*)scratch;
        state_out = out;
    }

    // PDL launch: k2 may start while k1 runs; k2 waits on the
    // programmatic edge before touching g_assign.
    cudaLaunchConfig_t cfg = {};
    cfg.gridDim  = dim3(BATCH, 1, 1);
    cfg.blockDim = dim3(256, 1, 1);
    cfg.dynamicSmemBytes = 0;
    cudaLaunchAttribute attrs[1];
    attrs[0].id = cudaLaunchAttributeProgrammaticStreamSerialization;
    attrs[0].val.programmaticStreamSerializationAllowed = 1;
    cfg.attrs    = attrs;
    cfg.numAttrs = 1;

    cudaLaunchKernelEx(&cfg, k2_fused,
                       prev_kc, curr_kc, prev_corr, kc_logits,
                       probs_out, state_out, do_state);
}

// round 11
// speedup vs baseline: 1.3780x; 1.3780x over previous
#include <cuda_runtime.h>
#include <math.h>

#define BATCH 256
#define TLEN  50
#define NOBS  8192
#define NKC   50

// ---- device-global scratch (no allocations allowed) ----
__device__ unsigned char g_assign[NOBS];                 // assign[] as uint8
__device__ float         g_probs_scratch[BATCH * TLEN];  // fallback sink

__device__ __forceinline__ float sigm(float x) {
    return 1.0f / (1.0f + __expf(-x));
}

// ============================================================
// k1: recover assign[] from one-hot A. Two independent float4
// loads per thread (MLP=2), 200 blocks x 256.
// ============================================================
__global__ __launch_bounds__(256)
void k1_prep(const float4* __restrict__ A4) {
    const int half = NOBS * NKC / 8;              // 51200 float4s per half
    int idx = blockIdx.x * 256 + threadIdx.x;
    float4 v0 = A4[idx];
    float4 v1 = A4[idx + half];

    int b0 = idx * 4;
    if (v0.x > 0.5f) { int i = b0 + 0; g_assign[i / NKC] = (unsigned char)(i % NKC); }
    if (v0.y > 0.5f) { int i = b0 + 1; g_assign[i / NKC] = (unsigned char)(i % NKC); }
    if (v0.z > 0.5f) { int i = b0 + 2; g_assign[i / NKC] = (unsigned char)(i % NKC); }
    if (v0.w > 0.5f) { int i = b0 + 3; g_assign[i / NKC] = (unsigned char)(i % NKC); }

    int b1 = (idx + half) * 4;
    if (v1.x > 0.5f) { int i = b1 + 0; g_assign[i / NKC] = (unsigned char)(i % NKC); }
    if (v1.y > 0.5f) { int i = b1 + 1; g_assign[i / NKC] = (unsigned char)(i % NKC); }
    if (v1.z > 0.5f) { int i = b1 + 2; g_assign[i / NKC] = (unsigned char)(i % NKC); }
    if (v1.w > 0.5f) { int i = b1 + 3; g_assign[i / NKC] = (unsigned char)(i % NKC); }
}

// ============================================================
// k2: fused BKT, one block (256 thr) per batch row.
//  - assign[pk]/assign[ck] gathered DIRECTLY from global (L2-hot)
//    as soon as pkv/ckv land — concurrent with the s_assign copy,
//    which is only needed by the expansion tail.
//  - parallel Moebius composition (r9-validated): pass A (out[t],
//    warps 0-1) and pass B (final state, warps 2-3), branch-free
//    select-to-identity, unroll 7.
//  - expansion: 8 uchar4 LDS gathers + 8 float4 stores per thread.
// ============================================================
__global__ __launch_bounds__(256)
void k2_fused(const int*   __restrict__ prev_kc,
              const int*   __restrict__ curr_kc,
              const float* __restrict__ prev_corr,
              const float* __restrict__ kc_logits,
              float*       __restrict__ probs_out,
              float*       __restrict__ state_out,
              int do_state) {
    __shared__ unsigned char s_assign[NOBS];   // 8 KB (expansion only)
    __shared__ float4        s_pr[NKC];        // sigmoid(pl,pf,p2,p3)
    __shared__ float         s_p4[NKC];        // initial state per KC
    __shared__ float4        s_M[TLEN];        // Moebius (A,B,C,D) per step
    __shared__ float2        s_ozw[TLEN];      // (q3-q2, q2) at ack KC
    __shared__ float         s_state[NKC];     // final compact state
    __shared__ unsigned char s_ap[TLEN];
    __shared__ unsigned char s_ack[TLEN];

    const int b   = blockIdx.x;
    const int tid = threadIdx.x;

    // ---- issue scalar row loads first ----
    int   pkv = 0, ckv = 0;
    float cr  = 0.0f;
    if (tid < TLEN) {
        pkv = prev_kc[b * TLEN + tid];
        ckv = curr_kc[b * TLEN + tid];
        cr  = prev_corr[b * TLEN + tid];
    }

    // ---- s_assign copy (expansion path only; overlaps everything) ----
    {
        const int4* src = (const int4*)g_assign;
        int4*       dst = (int4*)s_assign;
        dst[tid]       = src[tid];
        dst[tid + 256] = src[tid + 256];
    }

    // ---- sigmoids + DIRECT global gathers (concurrent with copy) ----
    int ap = 0, ac = 0;
    if (tid < TLEN) {
        float4 p;
        p.x = sigm(kc_logits[tid * 5 + 0]);
        p.y = sigm(kc_logits[tid * 5 + 1]);
        p.z = sigm(kc_logits[tid * 5 + 2]);
        p.w = sigm(kc_logits[tid * 5 + 3]);
        s_pr[tid] = p;
        s_p4[tid] = sigm(kc_logits[tid * 5 + 4]);

        ap = g_assign[pkv];       // L2-hit gather, no copy dependency
        ac = g_assign[ckv];
        s_ap[tid]  = (unsigned char)ap;
        s_ack[tid] = (unsigned char)ac;
    }
    __syncthreads();   // s_pr/s_p4 + s_ap/s_ack (+ s_assign) visible

    // ---- per-step Moebius tables ----
    if (tid < TLEN) {
        float4 pp = s_pr[ap];
        float o0, o1;
        if (cr > 0.5f) { o0 = pp.z;        o1 = pp.w;        }
        else           { o0 = 1.0f - pp.z; o1 = 1.0f - pp.w; }
        float d10 = o1 - o0;
        float c1  = 1.0f - pp.y - pp.x;
        // pred = (A*s + B) / (C*s + D)
        s_M[tid] = make_float4(fmaf(pp.x, d10, c1 * o1), pp.x * o0, d10, o0);

        float4 q = s_pr[ac];
        s_ozw[tid] = make_float2(q.w - q.z, q.z);
    }
    __syncthreads();

    // ---- parallel Moebius composition ----
    if (tid < TLEN) {
        // pass A: out[t], t = tid (t=0 -> identity)
        const int t = tid;
        const int k = (int)s_ack[t];
        float a = 1.0f, bm = 0.0f, c = 0.0f, d = 1.0f;
        #pragma unroll 7
        for (int i = 1; i < TLEN; i++) {
            float4 M = s_M[i];                            // broadcast LDS
            bool take = (i <= t) && ((int)s_ap[i] == k);
            float Mx = take ? M.x : 1.0f;
            float My = take ? M.y : 0.0f;
            float Mz = take ? M.z : 0.0f;
            float Mw = take ? M.w : 1.0f;
            float na = fmaf(Mx, a,  My * c);
            float nb = fmaf(Mx, bm, My * d);
            float nc = fmaf(Mz, a,  Mw * c);
            float nd = fmaf(Mz, bm, Mw * d);
            a = na; bm = nb; c = nc; d = nd;
        }
        float s0 = s_p4[k];
        float sf = __fdividef(fmaf(a, s0, bm), fmaf(c, s0, d));
        float2 zw = s_ozw[t];
        probs_out[b * TLEN + t] = fmaf(zw.x, sf, zw.y);
    } else if (tid >= 64 && tid < 64 + NKC) {
        // pass B: final state[k], k = tid-64 (separate warps)
        const int k = tid - 64;
        float a = 1.0f, bm = 0.0f, c = 0.0f, d = 1.0f;
        #pragma unroll 7
        for (int i = 1; i < TLEN; i++) {
            float4 M = s_M[i];
            bool take = ((int)s_ap[i] == k);
            float Mx = take ? M.x : 1.0f;
            float My = take ? M.y : 0.0f;
            float Mz = take ? M.z : 0.0f;
            float Mw = take ? M.w : 1.0f;
            float na = fmaf(Mx, a,  My * c);
            float nb = fmaf(Mx, bm, My * d);
            float nc = fmaf(Mz, a,  Mw * c);
            float nd = fmaf(Mz, bm, Mw * d);
            a = na; bm = nb; c = nc; d = nd;
        }
        float s0 = s_p4[k];
        s_state[k] = __fdividef(fmaf(a, s0, bm), fmaf(c, s0, d));
    }
    __syncthreads();

    // ---- expansion: 8 uchar4 LDS gathers + 8 float4 stores/thread ----
    if (do_state) {
        float4*       o  = (float4*)(state_out + (size_t)b * NOBS);
        const uchar4* a4 = (const uchar4*)s_assign;
        #pragma unroll
        for (int j = 0; j < 8; j++) {
            uchar4 a = a4[tid + 256 * j];
            o[tid + 256 * j] =
                make_float4(s_state[a.x], s_state[a.y], s_state[a.z], s_state[a.w]);
        }
    }
}

// ============================================================
extern "C" void kernel_launch(void* const* d_in, const int* in_sizes, int n_in,
                              void* d_out, int out_size) {
    const int*    prev_kc   = (const int*)   d_in[0];
    const int*    curr_kc   = (const int*)   d_in[1];
    const float*  prev_corr = (const float*) d_in[2];
    const float*  kc_logits = (const float*) d_in[3];
    const float4* A4        = (const float4*)d_in[4];
    float*        out       = (float*)d_out;

    k1_prep<<<(NOBS * NKC / 8) / 256, 256>>>(A4);

    // Output layout: [probs (256*50) | state (256*8192)] concatenated.
    float* probs_out = out;
    float* state_out = out + BATCH * TLEN;
    int    do_state  = 1;

    if (out_size == BATCH * TLEN) {
        do_state  = 0;
        state_out = out;                 // unused
    } else if (out_size == BATCH * NOBS) {
        void* scratch = nullptr;
        cudaGetSymbolAddress(&scratch, g_probs_scratch);
        probs_out = (float*)scratch;
        state_out = out;
    }

    k2_fused<<<BATCH, 256>>>(prev_kc, curr_kc, prev_corr, kc_logits,
                             probs_out, state_out, do_state);
}

// round 12
// speedup vs baseline: 1.3821x; 1.0030x over previous
#include <cuda_runtime.h>
#include <math.h>

#define BATCH 256
#define TLEN  50
#define NOBS  8192
#define NKC   50

// ---- device-global scratch (no allocations allowed) ----
__device__ unsigned char g_assign[NOBS];                 // assign[] as uint8
__device__ float         g_probs_scratch[BATCH * TLEN];  // fallback sink

__device__ __forceinline__ float sigm(float x) {
    return 1.0f / (1.0f + __expf(-x));
}

// ============================================================
// k1: recover assign[] from one-hot A. 100 blocks x 256 threads
// (SINGLE WAVE on 148 SMs), 4 independent float4 loads/thread.
// ============================================================
__global__ __launch_bounds__(256)
void k1_prep(const float4* __restrict__ A4) {
    const int stride = 100 * 256;                 // 25600 threads
    int t = blockIdx.x * 256 + threadIdx.x;
    #pragma unroll
    for (int j = 0; j < 4; j++) {
        int idx = t + stride * j;                 // < 102400
        float4 v = A4[idx];
        int base = idx * 4;
        if (v.x > 0.5f) { int i = base + 0; g_assign[i / NKC] = (unsigned char)(i % NKC); }
        if (v.y > 0.5f) { int i = base + 1; g_assign[i / NKC] = (unsigned char)(i % NKC); }
        if (v.z > 0.5f) { int i = base + 2; g_assign[i / NKC] = (unsigned char)(i % NKC); }
        if (v.w > 0.5f) { int i = base + 3; g_assign[i / NKC] = (unsigned char)(i % NKC); }
    }
}

// ============================================================
// k2: fused BKT. 128 blocks x 512 threads (SINGLE WAVE), each
// block processes TWO batch rows (one per 256-thread half).
// Pipeline per half = r11-validated:
//  - direct L2 gathers of assign[pk]/assign[ck] (no copy dep)
//  - per-step Moebius tables -> parallel composition (pass A:
//    out[t]; pass B: final state), branch-free, unroll 7
//  - expansion: 8 uchar4 LDS gathers + 8 float4 stores/thread
// s_assign copy + sigmoids shared per block.
// ============================================================
__global__ __launch_bounds__(512)
void k2_fused(const int*   __restrict__ prev_kc,
              const int*   __restrict__ curr_kc,
              const float* __restrict__ prev_corr,
              const float* __restrict__ kc_logits,
              float*       __restrict__ probs_out,
              float*       __restrict__ state_out,
              int do_state) {
    __shared__ unsigned char s_assign[NOBS];     // 8 KB (expansion only)
    __shared__ float4        s_pr[NKC];          // sigmoid(pl,pf,p2,p3)
    __shared__ float         s_p4[NKC];          // initial state per KC
    __shared__ float4        s_M[2][TLEN];       // Moebius per step, per row
    __shared__ float2        s_ozw[2][TLEN];     // (q3-q2, q2) per row
    __shared__ float         s_state[2][NKC];    // final compact state per row
    __shared__ unsigned char s_ap[2][TLEN];
    __shared__ unsigned char s_ack[2][TLEN];

    const int tid = threadIdx.x;
    const int r   = tid >> 8;          // row half: 0 or 1
    const int rt  = tid & 255;         // thread within half
    const int b   = blockIdx.x * 2 + r;

    // ---- issue scalar row loads first ----
    int   pkv = 0, ckv = 0;
    float cr  = 0.0f;
    if (rt < TLEN) {
        pkv = prev_kc[b * TLEN + rt];
        ckv = curr_kc[b * TLEN + rt];
        cr  = prev_corr[b * TLEN + rt];
    }

    // ---- s_assign copy (one int4 per thread = 8 KB; overlaps) ----
    {
        const int4* src = (const int4*)g_assign;
        int4*       dst = (int4*)s_assign;
        dst[tid] = src[tid];
    }

    // ---- sigmoids (once per block) ----
    if (tid < TLEN) {
        float4 p;
        p.x = sigm(kc_logits[tid * 5 + 0]);
        p.y = sigm(kc_logits[tid * 5 + 1]);
        p.z = sigm(kc_logits[tid * 5 + 2]);
        p.w = sigm(kc_logits[tid * 5 + 3]);
        s_pr[tid] = p;
        s_p4[tid] = sigm(kc_logits[tid * 5 + 4]);
    }

    // ---- direct L2 gathers (concurrent with copy) ----
    int ap = 0, ac = 0;
    if (rt < TLEN) {
        ap = g_assign[pkv];
        ac = g_assign[ckv];
        s_ap[r][rt]  = (unsigned char)ap;
        s_ack[r][rt] = (unsigned char)ac;
    }
    __syncthreads();

    // ---- per-step Moebius tables ----
    if (rt < TLEN) {
        float4 pp = s_pr[ap];
        float o0, o1;
        if (cr > 0.5f) { o0 = pp.z;        o1 = pp.w;        }
        else           { o0 = 1.0f - pp.z; o1 = 1.0f - pp.w; }
        float d10 = o1 - o0;
        float c1  = 1.0f - pp.y - pp.x;
        // pred = (A*s + B) / (C*s + D)
        s_M[r][rt] = make_float4(fmaf(pp.x, d10, c1 * o1), pp.x * o0, d10, o0);

        float4 q = s_pr[ac];
        s_ozw[r][rt] = make_float2(q.w - q.z, q.z);
    }
    __syncthreads();

    // ---- parallel Moebius composition (per half) ----
    if (rt < TLEN) {
        // pass A: out[t], t = rt (t=0 -> identity)
        const int t = rt;
        const int k = (int)s_ack[r][t];
        float a = 1.0f, bm = 0.0f, c = 0.0f, d = 1.0f;
        #pragma unroll 7
        for (int i = 1; i < TLEN; i++) {
            float4 M = s_M[r][i];                         // broadcast LDS
            bool take = (i <= t) && ((int)s_ap[r][i] == k);
            float Mx = take ? M.x : 1.0f;
            float My = take ? M.y : 0.0f;
            float Mz = take ? M.z : 0.0f;
            float Mw = take ? M.w : 1.0f;
            float na = fmaf(Mx, a,  My * c);
            float nb = fmaf(Mx, bm, My * d);
            float nc = fmaf(Mz, a,  Mw * c);
            float nd = fmaf(Mz, bm, Mw * d);
            a = na; bm = nb; c = nc; d = nd;
        }
        float s0 = s_p4[k];
        float sf = __fdividef(fmaf(a, s0, bm), fmaf(c, s0, d));
        float2 zw = s_ozw[r][t];
        probs_out[b * TLEN + t] = fmaf(zw.x, sf, zw.y);
    } else if (rt >= 64 && rt < 64 + NKC) {
        // pass B: final state[k], k = rt-64 (separate warps)
        const int k = rt - 64;
        float a = 1.0f, bm = 0.0f, c = 0.0f, d = 1.0f;
        #pragma unroll 7
        for (int i = 1; i < TLEN; i++) {
            float4 M = s_M[r][i];
            bool take = ((int)s_ap[r][i] == k);
            float Mx = take ? M.x : 1.0f;
            float My = take ? M.y : 0.0f;
            float Mz = take ? M.z : 0.0f;
            float Mw = take ? M.w : 1.0f;
            float na = fmaf(Mx, a,  My * c);
            float nb = fmaf(Mx, bm, My * d);
            float nc = fmaf(Mz, a,  Mw * c);
            float nd = fmaf(Mz, bm, Mw * d);
            a = na; bm = nb; c = nc; d = nd;
        }
        float s0 = s_p4[k];
        s_state[r][k] = __fdividef(fmaf(a, s0, bm), fmaf(c, s0, d));
    }
    __syncthreads();

    // ---- expansion: 8 uchar4 LDS gathers + 8 float4 stores/thread ----
    if (do_state) {
        float4*       o  = (float4*)(state_out + (size_t)b * NOBS);
        const uchar4* a4 = (const uchar4*)s_assign;
        const float*  st = s_state[r];
        #pragma unroll
        for (int j = 0; j < 8; j++) {
            uchar4 a = a4[rt + 256 * j];
            o[rt + 256 * j] =
                make_float4(st[a.x], st[a.y], st[a.z], st[a.w]);
        }
    }
}

// ============================================================
extern "C" void kernel_launch(void* const* d_in, const int* in_sizes, int n_in,
                              void* d_out, int out_size) {
    const int*    prev_kc   = (const int*)   d_in[0];
    const int*    curr_kc   = (const int*)   d_in[1];
    const float*  prev_corr = (const float*) d_in[2];
    const float*  kc_logits = (const float*) d_in[3];
    const float4* A4        = (const float4*)d_in[4];
    float*        out       = (float*)d_out;

    k1_prep<<<100, 256>>>(A4);

    // Output layout: [probs (256*50) | state (256*8192)] concatenated.
    float* probs_out = out;
    float* state_out = out + BATCH * TLEN;
    int    do_state  = 1;

    if (out_size == BATCH * TLEN) {
        do_state  = 0;
        state_out = out;                 // unused
    } else if (out_size == BATCH * NOBS) {
        void* scratch = nullptr;
        cudaGetSymbolAddress(&scratch, g_probs_scratch);
        probs_out = (float*)scratch;
        state_out = out;
    }

    k2_fused<<<BATCH / 2, 512>>>(prev_kc, curr_kc, prev_corr, kc_logits,
                                 probs_out, state_out, do_state);
}